// round 1
// baseline (speedup 1.0000x reference)
#include <cuda_runtime.h>
#include <math.h>

#define L   48
#define N3  110592              // 48^3
#define BF  128                 // B*CIN  = fields for x / Z
#define CF  256                 // CIN*COUT fields for Y

// ---------------- scratch (static device memory; no runtime allocation) ----
__device__ float2 g_tw[L * L];                 // e^{-2*pi*i*k*n/48}
__device__ float2 g_bufA[BF * N3];             // 113 MB
__device__ float2 g_bufB[BF * N3];             // 113 MB
__device__ float  g_Xh[BF * N3];               // 56.6 MB  (real spectral X)
__device__ float  g_Yh[CF * N3];               // 113 MB   (real spectral Y)
__device__ float  g_Z [BF * N3];               // 56.6 MB
__device__ float2 g_T1[CF * 12 * 12 * L];      // 14 MB
__device__ float2 g_T2[CF * 12 * L  * L];      // 56.6 MB

// ---------------- twiddle init (exact angles, double precision) ------------
__global__ void init_tw() {
    int idx = blockIdx.x * blockDim.x + threadIdx.x;
    if (idx < L * L) {
        int k = idx / L, n = idx % L;
        int m = (k * n) % L;
        double a = -6.283185307179586476925286766559 * (double)m / (double)L;
        g_tw[idx] = make_float2((float)cos(a), (float)sin(a));
    }
}

// ---------------- generic 48-point DFT pass (plane matmul in shared) -------
// Treats data as planes; transforms the "n" axis (stride ns) against the "j"
// axis (stride js). One of ns/js is 1; loads/stores are coalesced on it.
// RIN : input is real (imag = 0).  ROUT : output = scale*(Re - Im)  (DHT fold).
template<bool RIN, bool ROUT>
__global__ __launch_bounds__(256) void dft48(
    const float*  __restrict__ inR, const float2* __restrict__ inC,
    float*        __restrict__ outR, float2*      __restrict__ outC,
    int c1, long long ps0, long long ps1, int ns, int js, float scale)
{
    __shared__ float Cr[L][L + 1], Ci[L][L + 1];
    __shared__ float Pr[L][L + 1], Pi[L][L + 1];
    int t = threadIdx.x;
    long long base = (long long)(blockIdx.x / c1) * ps0
                   + (long long)(blockIdx.x % c1) * ps1;

    for (int idx = t; idx < L * L; idx += 256) {
        float2 c = g_tw[idx];
        Cr[idx / L][idx % L] = c.x;
        Ci[idx / L][idx % L] = c.y;
    }
    const bool nfast = (ns == 1);
    for (int idx = t; idx < L * L; idx += 256) {
        int f = idx % L, s = idx / L;            // f = fast gmem dim
        int n = nfast ? f : s;
        int j = nfast ? s : f;
        long long a = base + (long long)n * ns + (long long)j * js;
        if (RIN) {
            Pr[n][j] = inR[a];
        } else {
            float2 v = inC[a];
            Pr[n][j] = v.x;  Pi[n][j] = v.y;
        }
    }
    __syncthreads();

    int tx = t & 15, ty = t >> 4;
    int kb = nfast ? tx : ty;                    // k varies fastest on stride-1 dim
    int jb = nfast ? ty : tx;

    float accr[3][3] = {{0.f}}, acci[3][3] = {{0.f}};
    for (int n = 0; n < L; n++) {
        float cr[3], ci[3], pr[3], pi[3];
        #pragma unroll
        for (int a = 0; a < 3; a++) { cr[a] = Cr[kb + 16 * a][n]; ci[a] = Ci[kb + 16 * a][n]; }
        #pragma unroll
        for (int b = 0; b < 3; b++) {
            pr[b] = Pr[n][jb + 16 * b];
            if (!RIN) pi[b] = Pi[n][jb + 16 * b];
        }
        #pragma unroll
        for (int a = 0; a < 3; a++)
            #pragma unroll
            for (int b = 0; b < 3; b++) {
                if (RIN) {
                    accr[a][b] += cr[a] * pr[b];
                    acci[a][b] += ci[a] * pr[b];
                } else {
                    accr[a][b] += cr[a] * pr[b] - ci[a] * pi[b];
                    acci[a][b] += cr[a] * pi[b] + ci[a] * pr[b];
                }
            }
    }
    #pragma unroll
    for (int a = 0; a < 3; a++)
        #pragma unroll
        for (int b = 0; b < 3; b++) {
            int k = kb + 16 * a, j = jb + 16 * b;
            long long adr = base + (long long)k * ns + (long long)j * js;
            if (ROUT) outR[adr] = scale * (accr[a][b] - acci[a][b]);
            else      outC[adr] = make_float2(accr[a][b], acci[a][b]);
        }
}

// ---------------- Y path: factorized 12 -> 48 DFT of the weight block ------
__global__ void ykernel1(const float* __restrict__ w) {
    int idx = blockIdx.x * blockDim.x + threadIdx.x;
    if (idx >= CF * 12 * 12 * L) return;
    int k3 = idx % L;
    int r  = idx / L;                 // io*144 + n1*12 + n2
    const float* wp = w + r * 12;
    float ar = 0.f, ai = 0.f;
    #pragma unroll
    for (int n3 = 0; n3 < 12; n3++) {
        float2 e = g_tw[k3 * L + n3];
        float  v = wp[n3];
        ar += v * e.x;  ai += v * e.y;
    }
    g_T1[idx] = make_float2(ar, ai);
}

__global__ void ykernel2() {
    int idx = blockIdx.x * blockDim.x + threadIdx.x;
    if (idx >= CF * 12 * L * L) return;
    int k3 = idx % L;
    int k2 = (idx / L) % L;
    int r  = idx / (L * L);           // io*12 + n1
    float ar = 0.f, ai = 0.f;
    #pragma unroll
    for (int n2 = 0; n2 < 12; n2++) {
        float2 tv = g_T1[(r * 12 + n2) * L + k3];
        float2 e  = g_tw[k2 * L + n2];
        ar += tv.x * e.x - tv.y * e.y;
        ai += tv.x * e.y + tv.y * e.x;
    }
    g_T2[idx] = make_float2(ar, ai);
}

__global__ void ykernel3() {
    int idx = blockIdx.x * blockDim.x + threadIdx.x;
    if (idx >= CF * N3) return;
    int k3 = idx % L;
    int k2 = (idx / L) % L;
    int k1 = (idx / (L * L)) % L;
    int io = idx / N3;
    float ar = 0.f, ai = 0.f;
    #pragma unroll
    for (int n1 = 0; n1 < 12; n1++) {
        float2 tv = g_T2[((io * 12 + n1) * L + k2) * L + k3];
        float2 e  = g_tw[k1 * L + n1];
        ar += tv.x * e.x - tv.y * e.y;
        ai += tv.x * e.y + tv.y * e.x;
    }
    g_Yh[idx] = ar - ai;              // DHT fold: Re - Im
}

// ---------------- pointwise channel mix with flatten-flip ------------------
// Z[b,o,k] = sum_i 0.5*(X[k]+X[sk])*Y[k] + 0.5*(X[k]-X[sk])*Y[sk],  sk = (N-k)%N
__global__ __launch_bounds__(128) void mix_kernel() {
    __shared__ float Xa[4][128], Xb[4][128];     // [kk][b*16+i]
    __shared__ float Ya[4][256], Yb[4][256];     // [kk][i*16+o]
    int t  = threadIdx.x;
    int k0 = blockIdx.x * 4;

    for (int idx = t; idx < 512; idx += 128) {
        int bi = idx >> 2, kk = idx & 3;
        int k  = k0 + kk;
        int sk = (k == 0) ? 0 : (N3 - k);
        Xa[kk][bi] = g_Xh[(size_t)bi * N3 + k];
        Xb[kk][bi] = g_Xh[(size_t)bi * N3 + sk];
    }
    for (int idx = t; idx < 1024; idx += 128) {
        int io = idx >> 2, kk = idx & 3;
        int k  = k0 + kk;
        int sk = (k == 0) ? 0 : (N3 - k);
        Ya[kk][io] = g_Yh[(size_t)io * N3 + k];
        Yb[kk][io] = g_Yh[(size_t)io * N3 + sk];
    }
    __syncthreads();

    int b = t >> 4, o = t & 15;
    #pragma unroll
    for (int kk = 0; kk < 4; kk++) {
        float acc = 0.f;
        #pragma unroll
        for (int i = 0; i < 16; i++) {
            float xk = Xa[kk][b * 16 + i];
            float xs = Xb[kk][b * 16 + i];
            float xe = 0.5f * (xk + xs);
            float xo = 0.5f * (xk - xs);
            acc += xe * Ya[kk][i * 16 + o] + xo * Yb[kk][i * 16 + o];
        }
        g_Z[(size_t)(b * 16 + o) * N3 + k0 + kk] = acc;
    }
}

// ---------------- launcher -------------------------------------------------
extern "C" void kernel_launch(void* const* d_in, const int* in_sizes, int n_in,
                              void* d_out, int out_size) {
    (void)in_sizes; (void)n_in; (void)out_size;
    static float2* bufA = nullptr;
    static float2* bufB = nullptr;
    static float*  xh   = nullptr;
    static float*  z    = nullptr;
    if (!bufA) {   // resolved on the (non-captured) correctness call; cached after
        cudaGetSymbolAddress((void**)&bufA, g_bufA);
        cudaGetSymbolAddress((void**)&bufB, g_bufB);
        cudaGetSymbolAddress((void**)&xh,   g_Xh);
        cudaGetSymbolAddress((void**)&z,    g_Z);
    }
    const float* x  = (const float*)d_in[0];   // [8,16,48,48,48]
    const float* wt = (const float*)d_in[2];   // [16,16,12,12,12]
    float* out = (float*)d_out;                // [8,16,48,48,48]

    init_tw<<<(L * L + 255) / 256, 256>>>();

    // Y = DHT3(zero-padded weights), factorized 12->48 per axis
    ykernel1<<<(CF * 12 * 12 * L + 255) / 256, 256>>>(wt);
    ykernel2<<<(CF * 12 * L * L  + 255) / 256, 256>>>();
    ykernel3<<<(CF * N3          + 255) / 256, 256>>>();

    // forward 3D transform of x -> real Xh (Re - Im fused into last pass)
    dft48<true,  false><<<BF * 48, 256>>>(x, nullptr, nullptr, bufA,
                                          48, N3, 2304, 1,    48, 1.f);   // w axis
    dft48<false, false><<<BF * 48, 256>>>(nullptr, bufA, nullptr, bufB,
                                          48, N3, 2304, 48,   1,  1.f);   // h axis
    dft48<false, true ><<<BF * 48, 256>>>(nullptr, bufB, xh, nullptr,
                                          48, N3, 48,   2304, 1,  1.f);   // d axis

    // spectral channel mixing with flatten-flip pairing
    mix_kernel<<<N3 / 4, 128>>>();

    // inverse: DHT3(Z) / N3
    dft48<true,  false><<<BF * 48, 256>>>(z, nullptr, nullptr, bufA,
                                          48, N3, 2304, 1,    48, 1.f);
    dft48<false, false><<<BF * 48, 256>>>(nullptr, bufA, nullptr, bufB,
                                          48, N3, 2304, 48,   1,  1.f);
    dft48<false, true ><<<BF * 48, 256>>>(nullptr, bufB, out, nullptr,
                                          48, N3, 48,   2304, 1,  1.f / (float)N3);
}

// round 2
// speedup vs baseline: 1.4132x; 1.4132x over previous
#include <cuda_runtime.h>
#include <math.h>

#define L   48
#define N3  110592              // 48^3
#define BF  128                 // B*CIN  = fields for x / Z
#define CF  256                 // CIN*COUT fields for Y

// ---------------- scratch (static device memory; no runtime allocation) ----
__device__ float2 g_tw[L * L];                 // W48^{(k*n)%48} full table (Y path小 kernels)
__device__ float2 g_tw1[L];                    // W48^m, 1-D table
__device__ float2 g_emp[L];                    // (Re-Im fold): (cx-cy, cx+cy)
__device__ float2 g_bufA[BF * N3];             // 113 MB
__device__ float2 g_bufB[BF * N3];             // 113 MB
__device__ float  g_Xh[BF * N3];               // 56.6 MB  (real spectral X)
__device__ float  g_Yh[CF * N3];               // 113 MB   (real spectral Y)
__device__ float  g_Z [BF * N3];               // 56.6 MB
__device__ float2 g_T1[CF * 12 * 12 * L];      // 14 MB
__device__ float2 g_T2[CF * 12 * L  * L];      // 56.6 MB

// ---------------- twiddle init (exact angles, double precision) ------------
__global__ void init_tw() {
    int idx = blockIdx.x * blockDim.x + threadIdx.x;
    if (idx < L * L) {
        int k = idx / L, n = idx % L;
        int m = (k * n) % L;
        double a = -6.283185307179586476925286766559 * (double)m / (double)L;
        g_tw[idx] = make_float2((float)cos(a), (float)sin(a));
    }
    if (idx < L) {
        double a = -6.283185307179586476925286766559 * (double)idx / (double)L;
        float cx = (float)cos(a), cy = (float)sin(a);
        g_tw1[idx] = make_float2(cx, cy);
        g_emp[idx] = make_float2(cx - cy, cx + cy);
    }
}

// ---------------- radix-8x6 48-point DFT pass (two stages in shared) -------
// Plane: transform axis "n" (stride ns) x batch axis "j" (stride js).
// RIN : input real.  ROUT : output = scale*(Re - Im)  (DHT fold, 2 FMA/tap).
template<bool RIN, bool ROUT>
__global__ __launch_bounds__(256) void dft48r(
    const float*  __restrict__ inR, const float2* __restrict__ inC,
    float*        __restrict__ outR, float2*      __restrict__ outC,
    int c1, long long ps0, long long ps1, int ns, int js, float scale)
{
    __shared__ float  Pr[L][L + 1], Pi[L][L + 1];
    __shared__ float  Ar[L][L + 1], Ai[L][L + 1];
    __shared__ float2 TW[L];     // W48^m
    __shared__ float2 EMP[L];    // (cx-cy, cx+cy)

    int t = threadIdx.x;
    long long base = (long long)(blockIdx.x / c1) * ps0
                   + (long long)(blockIdx.x % c1) * ps1;

    if (t < L) { TW[t] = g_tw1[t]; EMP[t] = g_emp[t]; }

    const bool nfast = (ns == 1);
    for (int idx = t; idx < L * L; idx += 256) {
        int f = idx % L, s = idx / L;            // f = fast gmem dim
        int n = nfast ? f : s;
        int j = nfast ? s : f;
        long long a = base + (long long)n * ns + (long long)j * js;
        if (RIN) {
            Pr[n][j] = inR[a];
        } else {
            float2 v = inC[a];
            Pr[n][j] = v.x;  Pi[n][j] = v.y;
        }
    }
    __syncthreads();

    int tx = t & 15, ty = t >> 4;
    int k1 = ty & 7;                 // k mod 8 : identical for rows ty, ty+16, ty+32

    // ---- stage 1: A[m][j] = sum_{n1<8} P[6*n1 + (m>>3)][j] * W48^{6*n1*(m&7)}
    {
        float ar[3][3] = {{0.f}}, ai[3][3] = {{0.f}};
        #pragma unroll
        for (int n1 = 0; n1 < 8; n1++) {
            float2 w = TW[(6 * n1 * k1) % L];
            #pragma unroll
            for (int a = 0; a < 3; a++) {
                int n2  = (ty + 16 * a) >> 3;
                int row = 6 * n1 + n2;
                #pragma unroll
                for (int b = 0; b < 3; b++) {
                    float pr = Pr[row][tx + 16 * b];
                    if (RIN) {
                        ar[a][b] += pr * w.x;
                        ai[a][b] += pr * w.y;
                    } else {
                        float pi = Pi[row][tx + 16 * b];
                        ar[a][b] += pr * w.x - pi * w.y;
                        ai[a][b] += pr * w.y + pi * w.x;
                    }
                }
            }
        }
        #pragma unroll
        for (int a = 0; a < 3; a++)
            #pragma unroll
            for (int b = 0; b < 3; b++) {
                Ar[ty + 16 * a][tx + 16 * b] = ar[a][b];
                Ai[ty + 16 * a][tx + 16 * b] = ai[a][b];
            }
    }
    __syncthreads();

    // ---- stage 2: X[k][j] = sum_{n2<6} A[n2*8 + (k&7)][j] * W48^{n2*k}
    {
        float accr[3][3] = {{0.f}}, acci[3][3] = {{0.f}};
        #pragma unroll
        for (int n2 = 0; n2 < 6; n2++) {
            int arow = n2 * 8 + k1;
            float av[3], bv[3];
            #pragma unroll
            for (int b = 0; b < 3; b++) {
                av[b] = Ar[arow][tx + 16 * b];
                bv[b] = Ai[arow][tx + 16 * b];
            }
            #pragma unroll
            for (int a = 0; a < 3; a++) {
                int k = ty + 16 * a;
                int widx = (n2 * k) % L;
                if (ROUT) {
                    float2 e = EMP[widx];
                    #pragma unroll
                    for (int b = 0; b < 3; b++)
                        accr[a][b] += av[b] * e.x - bv[b] * e.y;
                } else {
                    float2 w = TW[widx];
                    #pragma unroll
                    for (int b = 0; b < 3; b++) {
                        accr[a][b] += av[b] * w.x - bv[b] * w.y;
                        acci[a][b] += av[b] * w.y + bv[b] * w.x;
                    }
                }
            }
        }
        #pragma unroll
        for (int a = 0; a < 3; a++)
            #pragma unroll
            for (int b = 0; b < 3; b++) {
                int k = ty + 16 * a, j = tx + 16 * b;
                long long adr = base + (long long)k * ns + (long long)j * js;
                if (ROUT) outR[adr] = scale * accr[a][b];
                else      outC[adr] = make_float2(accr[a][b], acci[a][b]);
            }
    }
}

// ---------------- Y path: factorized 12 -> 48 DFT of the weight block ------
__global__ void ykernel1(const float* __restrict__ w) {
    int idx = blockIdx.x * blockDim.x + threadIdx.x;
    if (idx >= CF * 12 * 12 * L) return;
    int k3 = idx % L;
    int r  = idx / L;                 // io*144 + n1*12 + n2
    const float* wp = w + r * 12;
    float ar = 0.f, ai = 0.f;
    #pragma unroll
    for (int n3 = 0; n3 < 12; n3++) {
        float2 e = g_tw[k3 * L + n3];
        float  v = wp[n3];
        ar += v * e.x;  ai += v * e.y;
    }
    g_T1[idx] = make_float2(ar, ai);
}

__global__ void ykernel2() {
    int idx = blockIdx.x * blockDim.x + threadIdx.x;
    if (idx >= CF * 12 * L * L) return;
    int k3 = idx % L;
    int k2 = (idx / L) % L;
    int r  = idx / (L * L);           // io*12 + n1
    float ar = 0.f, ai = 0.f;
    #pragma unroll
    for (int n2 = 0; n2 < 12; n2++) {
        float2 tv = g_T1[(r * 12 + n2) * L + k3];
        float2 e  = g_tw[k2 * L + n2];
        ar += tv.x * e.x - tv.y * e.y;
        ai += tv.x * e.y + tv.y * e.x;
    }
    g_T2[idx] = make_float2(ar, ai);
}

// tiled final Y pass: out[io,k1,k2,k3] = fold( sum_{n1<12} T2[io,n1,k2,k3]*W48^{n1*k1} )
__global__ __launch_bounds__(256) void ykernel3t() {
    __shared__ float  Tr[12][L + 1], Ti[12][L + 1];
    __shared__ float2 EMP[L];
    int t  = threadIdx.x;
    int io = blockIdx.x / L;
    int k2 = blockIdx.x % L;

    if (t < L) EMP[t] = g_emp[t];
    for (int idx = t; idx < 12 * L; idx += 256) {
        int n1 = idx / L, c = idx % L;
        float2 v = g_T2[(size_t)((io * 12 + n1) * L + k2) * L + c];
        Tr[n1][c] = v.x;  Ti[n1][c] = v.y;
    }
    __syncthreads();

    int tx = t & 15, ty = t >> 4;
    float acc[3][3] = {{0.f}};
    #pragma unroll
    for (int n1 = 0; n1 < 12; n1++) {
        float tv[3], ui[3];
        #pragma unroll
        for (int b = 0; b < 3; b++) { tv[b] = Tr[n1][tx + 16 * b]; ui[b] = Ti[n1][tx + 16 * b]; }
        #pragma unroll
        for (int a = 0; a < 3; a++) {
            float2 e = EMP[(n1 * (ty + 16 * a)) % L];
            #pragma unroll
            for (int b = 0; b < 3; b++)
                acc[a][b] += tv[b] * e.x - ui[b] * e.y;
        }
    }
    #pragma unroll
    for (int a = 0; a < 3; a++)
        #pragma unroll
        for (int b = 0; b < 3; b++)
            g_Yh[(size_t)io * N3 + (size_t)(ty + 16 * a) * 2304 + k2 * L + tx + 16 * b] = acc[a][b];
}

// ---------------- pointwise channel mix with flatten-flip ------------------
__global__ __launch_bounds__(128) void mix_kernel() {
    __shared__ float Xa[4][128], Xb[4][128];     // [kk][b*16+i]
    __shared__ float Ya[4][256], Yb[4][256];     // [kk][i*16+o]
    int t  = threadIdx.x;
    int k0 = blockIdx.x * 4;

    for (int idx = t; idx < 512; idx += 128) {
        int bi = idx >> 2, kk = idx & 3;
        int k  = k0 + kk;
        int sk = (k == 0) ? 0 : (N3 - k);
        Xa[kk][bi] = g_Xh[(size_t)bi * N3 + k];
        Xb[kk][bi] = g_Xh[(size_t)bi * N3 + sk];
    }
    for (int idx = t; idx < 1024; idx += 128) {
        int io = idx >> 2, kk = idx & 3;
        int k  = k0 + kk;
        int sk = (k == 0) ? 0 : (N3 - k);
        Ya[kk][io] = g_Yh[(size_t)io * N3 + k];
        Yb[kk][io] = g_Yh[(size_t)io * N3 + sk];
    }
    __syncthreads();

    int b = t >> 4, o = t & 15;
    #pragma unroll
    for (int kk = 0; kk < 4; kk++) {
        float acc = 0.f;
        #pragma unroll
        for (int i = 0; i < 16; i++) {
            float xk = Xa[kk][b * 16 + i];
            float xs = Xb[kk][b * 16 + i];
            float xe = 0.5f * (xk + xs);
            float xo = 0.5f * (xk - xs);
            acc += xe * Ya[kk][i * 16 + o] + xo * Yb[kk][i * 16 + o];
        }
        g_Z[(size_t)(b * 16 + o) * N3 + k0 + kk] = acc;
    }
}

// ---------------- launcher -------------------------------------------------
extern "C" void kernel_launch(void* const* d_in, const int* in_sizes, int n_in,
                              void* d_out, int out_size) {
    (void)in_sizes; (void)n_in; (void)out_size;
    static float2* bufA = nullptr;
    static float2* bufB = nullptr;
    static float*  xh   = nullptr;
    static float*  z    = nullptr;
    if (!bufA) {
        cudaGetSymbolAddress((void**)&bufA, g_bufA);
        cudaGetSymbolAddress((void**)&bufB, g_bufB);
        cudaGetSymbolAddress((void**)&xh,   g_Xh);
        cudaGetSymbolAddress((void**)&z,    g_Z);
    }
    const float* x  = (const float*)d_in[0];   // [8,16,48,48,48]
    const float* wt = (const float*)d_in[2];   // [16,16,12,12,12]
    float* out = (float*)d_out;                // [8,16,48,48,48]

    init_tw<<<(L * L + 255) / 256, 256>>>();

    // Y = DHT3(zero-padded weights), factorized 12->48 per axis
    ykernel1<<<(CF * 12 * 12 * L + 255) / 256, 256>>>(wt);
    ykernel2<<<(CF * 12 * L * L  + 255) / 256, 256>>>();
    ykernel3t<<<CF * L, 256>>>();

    // forward 3D transform of x -> real Xh (Re - Im fused into last pass)
    dft48r<true,  false><<<BF * 48, 256>>>(x, nullptr, nullptr, bufA,
                                           48, N3, 2304, 1,    48, 1.f);   // w axis
    dft48r<false, false><<<BF * 48, 256>>>(nullptr, bufA, nullptr, bufB,
                                           48, N3, 2304, 48,   1,  1.f);   // h axis
    dft48r<false, true ><<<BF * 48, 256>>>(nullptr, bufB, xh, nullptr,
                                           48, N3, 48,   2304, 1,  1.f);   // d axis

    // spectral channel mixing with flatten-flip pairing
    mix_kernel<<<N3 / 4, 128>>>();

    // inverse: DHT3(Z) / N3
    dft48r<true,  false><<<BF * 48, 256>>>(z, nullptr, nullptr, bufA,
                                           48, N3, 2304, 1,    48, 1.f);
    dft48r<false, false><<<BF * 48, 256>>>(nullptr, bufA, nullptr, bufB,
                                           48, N3, 2304, 48,   1,  1.f);
    dft48r<false, true ><<<BF * 48, 256>>>(nullptr, bufB, out, nullptr,
                                           48, N3, 48,   2304, 1,  1.f / (float)N3);
}

// round 4
// speedup vs baseline: 2.2910x; 1.6211x over previous
#include <cuda_runtime.h>
#include <math.h>

#define L    48
#define LH   26                 // kept frequencies (Hermitian half: 0..25)
#define N3   110592             // 48^3
#define BF   128                // B*CIN  fields for x / Z
#define CF   256                // CIN*COUT fields for Y
#define PLH  59904              // 48*48*26  (per-field half-spectrum elems)

// ---------------- scratch (static device memory) ---------------------------
__device__ float2 g_tw[L * L];                 // W48^{(k*n)%48} (Y path)
__device__ float2 g_tw1[L];                    // W48^m
__device__ float2 g_emp[L];                    // fold table: (cx-cy, cx+cy)
__device__ float2 g_bufA[BF * PLH];            // 61 MB
__device__ float2 g_bufB[BF * PLH];            // 61 MB
__device__ float  g_Xh[BF * N3];               // 56.6 MB
__device__ float  g_Yh[CF * N3];               // 113 MB
__device__ float  g_Z [BF * N3];               // 56.6 MB
__device__ float2 g_T1[CF * 12 * 12 * L];
__device__ float2 g_T2[CF * 12 * L * L];

// ---------------- twiddle init ---------------------------------------------
__global__ void init_tw() {
    int idx = blockIdx.x * blockDim.x + threadIdx.x;
    if (idx < L * L) {
        int k = idx / L, n = idx % L;
        int m = (k * n) % L;
        double a = -6.283185307179586476925286766559 * (double)m / (double)L;
        g_tw[idx] = make_float2((float)cos(a), (float)sin(a));
    }
    if (idx < L) {
        double a = -6.283185307179586476925286766559 * (double)idx / (double)L;
        float cx = (float)cos(a), cy = (float)sin(a);
        g_tw1[idx] = make_float2(cx, cy);
        g_emp[idx] = make_float2(cx - cy, cx + cy);
    }
}

// ============ pass W: real input, DFT along w, keep k3 in [0,25] ============
// block = (field, d).  Transform axis = w (P's FIRST index).
// out[(f*48+d)*48*26 + h*26 + k3]  (complex), layout [f][d][h][k_w]
__global__ __launch_bounds__(256) void pass_w(
    const float* __restrict__ in, float2* __restrict__ out)
{
    __shared__ float  P[L][L + 1];       // P[w][h]
    __shared__ float2 A2[L][L + 2];
    __shared__ float2 TWs[L];
    int t = threadIdx.x;
    int f = blockIdx.x / L, d = blockIdx.x % L;
    const float* src = in + (size_t)f * N3 + (size_t)d * 2304;

    if (t < L) TWs[t] = g_tw1[t];
    for (int idx = t; idx < L * L; idx += 256)
        P[idx % L][idx / L] = src[idx];            // TRANSPOSED: P[w][h]
    __syncthreads();

    int tx = t & 15, ty = t >> 4;

    // stage 1: A[m][h], m = ty+16a (k1 = ty&7 uniform), h = tx+16b
    {
        int k1 = ty & 7;
        float2 w8[8];
        int step = (6 * k1) % L, widx = 0;
        #pragma unroll
        for (int n1 = 0; n1 < 8; n1++) { w8[n1] = TWs[widx]; widx += step; if (widx >= L) widx -= L; }

        float ar[3][3] = {{0.f}}, ai[3][3] = {{0.f}};
        #pragma unroll
        for (int n1 = 0; n1 < 8; n1++) {
            float2 w = w8[n1];
            #pragma unroll
            for (int a = 0; a < 3; a++) {
                int row = 6 * n1 + ((ty + 16 * a) >> 3);
                #pragma unroll
                for (int b = 0; b < 3; b++) {
                    float p = P[row][tx + 16 * b];
                    ar[a][b] += p * w.x;  ai[a][b] += p * w.y;
                }
            }
        }
        #pragma unroll
        for (int a = 0; a < 3; a++)
            #pragma unroll
            for (int b = 0; b < 3; b++)
                A2[ty + 16 * a][tx + 16 * b] = make_float2(ar[a][b], ai[a][b]);
    }
    __syncthreads();

    // stage 2: k3 = tx+16c (c<2, k3<26), h = ty+16a
    {
        float xr[3][2] = {{0.f}}, xi[3][2] = {{0.f}};
        int r8 = tx & 7;
        int i0 = 0, i1 = 0;
        int k3a = tx, k3b = tx + 16;
        #pragma unroll
        for (int n2 = 0; n2 < 6; n2++) {
            int arow = n2 * 8 + r8;
            float2 w0 = TWs[i0], w1 = TWs[i1];
            i0 += k3a; if (i0 >= L) i0 -= L;
            i1 += k3b; if (i1 >= L) i1 -= L;
            #pragma unroll
            for (int a = 0; a < 3; a++) {
                float2 v = A2[arow][ty + 16 * a];
                xr[a][0] += v.x * w0.x - v.y * w0.y;
                xi[a][0] += v.x * w0.y + v.y * w0.x;
                xr[a][1] += v.x * w1.x - v.y * w1.y;
                xi[a][1] += v.x * w1.y + v.y * w1.x;
            }
        }
        float2* dst = out + (size_t)(f * L + d) * (L * LH);
        bool g1 = (tx < 10);
        #pragma unroll
        for (int a = 0; a < 3; a++) {
            int h = ty + 16 * a;
            dst[(size_t)h * LH + k3a] = make_float2(xr[a][0], xi[a][0]);
            if (g1) dst[(size_t)h * LH + k3b] = make_float2(xr[a][1], xi[a][1]);
        }
    }
}

// ============ pass H: complex, DFT along h, 26 columns ======================
// block = (field, d).  in [f][d][h][k_w]  ->  out [f][d][k_h][k_w]
__global__ __launch_bounds__(256) void pass_h(
    const float2* __restrict__ in, float2* __restrict__ out)
{
    __shared__ float2 Q2[L][LH + 1];
    __shared__ float2 A2[L][LH + 1];
    __shared__ float2 TWs[L];
    int t = threadIdx.x;
    size_t base = (size_t)blockIdx.x * (L * LH);
    const float2* src = in + base;

    if (t < L) TWs[t] = g_tw1[t];
    for (int idx = t; idx < L * LH; idx += 256)
        Q2[idx / LH][idx % LH] = src[idx];
    __syncthreads();

    int tx = t & 15, ty = t >> 4;
    bool g1 = (tx < 10);

    // stage 1: m = ty+16a, j = tx+16b (b<2 guarded)
    {
        int k1 = ty & 7;
        float2 w8[8];
        int step = (6 * k1) % L, widx = 0;
        #pragma unroll
        for (int n1 = 0; n1 < 8; n1++) { w8[n1] = TWs[widx]; widx += step; if (widx >= L) widx -= L; }

        float ar[3][2] = {{0.f}}, ai[3][2] = {{0.f}};
        #pragma unroll
        for (int n1 = 0; n1 < 8; n1++) {
            float2 w = w8[n1];
            #pragma unroll
            for (int a = 0; a < 3; a++) {
                int row = 6 * n1 + ((ty + 16 * a) >> 3);
                #pragma unroll
                for (int b = 0; b < 2; b++) {
                    float2 q = Q2[row][tx + 16 * b];
                    ar[a][b] += q.x * w.x - q.y * w.y;
                    ai[a][b] += q.x * w.y + q.y * w.x;
                }
            }
        }
        #pragma unroll
        for (int a = 0; a < 3; a++) {
            A2[ty + 16 * a][tx]      = make_float2(ar[a][0], ai[a][0]);
            if (g1) A2[ty + 16 * a][tx + 16] = make_float2(ar[a][1], ai[a][1]);
        }
    }
    __syncthreads();

    // stage 2: k2 = ty+16a (full 48), j = tx+16b
    {
        int r8 = ty & 7;
        float xr[3][2] = {{0.f}}, xi[3][2] = {{0.f}};
        int iw[3] = {0, 0, 0};
        #pragma unroll
        for (int n2 = 0; n2 < 6; n2++) {
            int arow = n2 * 8 + r8;
            float2 v0 = A2[arow][tx];
            float2 v1 = A2[arow][tx + 16];
            #pragma unroll
            for (int a = 0; a < 3; a++) {
                float2 w = TWs[iw[a]];
                iw[a] += ty + 16 * a; if (iw[a] >= L) iw[a] -= L;
                xr[a][0] += v0.x * w.x - v0.y * w.y;
                xi[a][0] += v0.x * w.y + v0.y * w.x;
                xr[a][1] += v1.x * w.x - v1.y * w.y;
                xi[a][1] += v1.x * w.y + v1.y * w.x;
            }
        }
        float2* dst = out + base;
        #pragma unroll
        for (int a = 0; a < 3; a++) {
            int k2 = ty + 16 * a;
            dst[(size_t)k2 * LH + tx] = make_float2(xr[a][0], xi[a][0]);
            if (g1) dst[(size_t)k2 * LH + tx + 16] = make_float2(xr[a][1], xi[a][1]);
        }
    }
}

// ============ pass D: complex, DFT along d, fold + Hermitian mirror write ===
// block = (field, k_h).  in [f][d][k_h][k_w]; out real full volume [k_d][k_h][k_w]
__global__ __launch_bounds__(256) void pass_d(
    const float2* __restrict__ in, float* __restrict__ out, float scale)
{
    __shared__ float2 Q2[L][LH + 1];
    __shared__ float2 A2[L][LH + 1];
    __shared__ float2 TWs[L];
    int t = threadIdx.x;
    int f = blockIdx.x / L, k2 = blockIdx.x % L;     // k2 = k_h row
    const float2* src = in + ((size_t)f * (L * L) + k2) * LH;

    if (t < L) TWs[t] = g_tw1[t];
    for (int idx = t; idx < L * LH; idx += 256)
        Q2[idx / LH][idx % LH] = src[(size_t)(idx / LH) * (L * LH) + (idx % LH)];
    __syncthreads();

    int tx = t & 15, ty = t >> 4;
    bool g1 = (tx < 10);

    // stage 1
    {
        int k1 = ty & 7;
        float2 w8[8];
        int step = (6 * k1) % L, widx = 0;
        #pragma unroll
        for (int n1 = 0; n1 < 8; n1++) { w8[n1] = TWs[widx]; widx += step; if (widx >= L) widx -= L; }

        float ar[3][2] = {{0.f}}, ai[3][2] = {{0.f}};
        #pragma unroll
        for (int n1 = 0; n1 < 8; n1++) {
            float2 w = w8[n1];
            #pragma unroll
            for (int a = 0; a < 3; a++) {
                int row = 6 * n1 + ((ty + 16 * a) >> 3);
                #pragma unroll
                for (int b = 0; b < 2; b++) {
                    float2 q = Q2[row][tx + 16 * b];
                    ar[a][b] += q.x * w.x - q.y * w.y;
                    ai[a][b] += q.x * w.y + q.y * w.x;
                }
            }
        }
        #pragma unroll
        for (int a = 0; a < 3; a++) {
            A2[ty + 16 * a][tx]      = make_float2(ar[a][0], ai[a][0]);
            if (g1) A2[ty + 16 * a][tx + 16] = make_float2(ar[a][1], ai[a][1]);
        }
    }
    __syncthreads();

    // stage 2 + fold: k1 = ty+16a (k_d), k3 = tx+16b (k_w)
    {
        int r8 = ty & 7;
        float xr[3][2] = {{0.f}}, xi[3][2] = {{0.f}};
        int iw[3] = {0, 0, 0};
        #pragma unroll
        for (int n2 = 0; n2 < 6; n2++) {
            int arow = n2 * 8 + r8;
            float2 v0 = A2[arow][tx];
            float2 v1 = A2[arow][tx + 16];
            #pragma unroll
            for (int a = 0; a < 3; a++) {
                float2 w = TWs[iw[a]];
                iw[a] += ty + 16 * a; if (iw[a] >= L) iw[a] -= L;
                xr[a][0] += v0.x * w.x - v0.y * w.y;
                xi[a][0] += v0.x * w.y + v0.y * w.x;
                xr[a][1] += v1.x * w.x - v1.y * w.y;
                xi[a][1] += v1.x * w.y + v1.y * w.x;
            }
        }
        int mk2 = (k2 == 0) ? 0 : L - k2;
        float* dstD = out + (size_t)f * N3 + (size_t)k2 * L;
        float* dstM = out + (size_t)f * N3 + (size_t)mk2 * L;
        int k3a = tx, k3b = tx + 16;
        int m3a = (k3a == 0) ? 0 : L - k3a;
        int m3b = L - k3b;
        #pragma unroll
        for (int a = 0; a < 3; a++) {
            int k1 = ty + 16 * a;
            int mk1 = (k1 == 0) ? 0 : L - k1;
            dstD[(size_t)k1 * 2304 + k3a]  = scale * (xr[a][0] - xi[a][0]);
            dstM[(size_t)mk1 * 2304 + m3a] = scale * (xr[a][0] + xi[a][0]);
            if (g1) {
                dstD[(size_t)k1 * 2304 + k3b]  = scale * (xr[a][1] - xi[a][1]);
                dstM[(size_t)mk1 * 2304 + m3b] = scale * (xr[a][1] + xi[a][1]);
            }
        }
    }
}

// ---------------- Y path ----------------------------------------------------
__global__ void ykernel1(const float* __restrict__ w) {
    int idx = blockIdx.x * blockDim.x + threadIdx.x;
    if (idx >= CF * 12 * 12 * L) return;
    int k3 = idx % L;
    int r  = idx / L;
    const float* wp = w + r * 12;
    float ar = 0.f, ai = 0.f;
    #pragma unroll
    for (int n3 = 0; n3 < 12; n3++) {
        float2 e = g_tw[k3 * L + n3];
        float  v = wp[n3];
        ar += v * e.x;  ai += v * e.y;
    }
    g_T1[idx] = make_float2(ar, ai);
}

__global__ void ykernel2() {
    int idx = blockIdx.x * blockDim.x + threadIdx.x;
    if (idx >= CF * 12 * L * L) return;
    int k3 = idx % L;
    int k2 = (idx / L) % L;
    int r  = idx / (L * L);
    float ar = 0.f, ai = 0.f;
    #pragma unroll
    for (int n2 = 0; n2 < 12; n2++) {
        float2 tv = g_T1[(r * 12 + n2) * L + k3];
        float2 e  = g_tw[k2 * L + n2];
        ar += tv.x * e.x - tv.y * e.y;
        ai += tv.x * e.y + tv.y * e.x;
    }
    g_T2[idx] = make_float2(ar, ai);
}

__global__ __launch_bounds__(256) void ykernel3t() {
    __shared__ float  Tr[12][L + 1], Ti[12][L + 1];
    __shared__ float2 EMP[L];
    int t  = threadIdx.x;
    int io = blockIdx.x / L;
    int k2 = blockIdx.x % L;

    if (t < L) EMP[t] = g_emp[t];
    for (int idx = t; idx < 12 * L; idx += 256) {
        int n1 = idx / L, c = idx % L;
        float2 v = g_T2[(size_t)((io * 12 + n1) * L + k2) * L + c];
        Tr[n1][c] = v.x;  Ti[n1][c] = v.y;
    }
    __syncthreads();

    int tx = t & 15, ty = t >> 4;
    float acc[3][3] = {{0.f}};
    int iw[3] = {0, 0, 0};
    #pragma unroll
    for (int n1 = 0; n1 < 12; n1++) {
        float tv[3], ui[3];
        #pragma unroll
        for (int b = 0; b < 3; b++) { tv[b] = Tr[n1][tx + 16 * b]; ui[b] = Ti[n1][tx + 16 * b]; }
        #pragma unroll
        for (int a = 0; a < 3; a++) {
            float2 e = EMP[iw[a]];
            iw[a] += ty + 16 * a; if (iw[a] >= L) iw[a] -= L;
            #pragma unroll
            for (int b = 0; b < 3; b++)
                acc[a][b] += tv[b] * e.x - ui[b] * e.y;
        }
    }
    #pragma unroll
    for (int a = 0; a < 3; a++)
        #pragma unroll
        for (int b = 0; b < 3; b++)
            g_Yh[(size_t)io * N3 + (size_t)(ty + 16 * a) * 2304 + k2 * L + tx + 16 * b] = acc[a][b];
}

// ---------------- paired pointwise mix --------------------------------------
__global__ __launch_bounds__(128) void mix2() {
    __shared__ float Xa[4][128], Xb[4][128];
    __shared__ float Ya[4][256], Yb[4][256];
    int t  = threadIdx.x;
    int k0 = blockIdx.x * 4;

    for (int idx = t; idx < 512; idx += 128) {
        int bi = idx >> 2, kk = idx & 3;
        int k  = k0 + kk; if (k > 55296) k = 55296;
        int sk = (k == 0) ? 0 : (N3 - k);
        Xa[kk][bi] = g_Xh[(size_t)bi * N3 + k];
        Xb[kk][bi] = g_Xh[(size_t)bi * N3 + sk];
    }
    for (int idx = t; idx < 1024; idx += 128) {
        int io = idx >> 2, kk = idx & 3;
        int k  = k0 + kk; if (k > 55296) k = 55296;
        int sk = (k == 0) ? 0 : (N3 - k);
        Ya[kk][io] = g_Yh[(size_t)io * N3 + k];
        Yb[kk][io] = g_Yh[(size_t)io * N3 + sk];
    }
    __syncthreads();

    int b = t >> 4, o = t & 15;
    #pragma unroll
    for (int kk = 0; kk < 4; kk++) {
        int k  = k0 + kk; if (k > 55296) k = 55296;
        int sk = (k == 0) ? 0 : (N3 - k);
        float acc = 0.f, accs = 0.f;
        #pragma unroll
        for (int i = 0; i < 16; i++) {
            float xk = Xa[kk][b * 16 + i];
            float xs = Xb[kk][b * 16 + i];
            float xe = 0.5f * (xk + xs);
            float xo = 0.5f * (xk - xs);
            float yk = Ya[kk][i * 16 + o];
            float ys = Yb[kk][i * 16 + o];
            acc  += xe * yk + xo * ys;
            accs += xe * ys - xo * yk;
        }
        g_Z[(size_t)(b * 16 + o) * N3 + k]  = acc;
        g_Z[(size_t)(b * 16 + o) * N3 + sk] = accs;
    }
}

// ---------------- launcher ---------------------------------------------------
extern "C" void kernel_launch(void* const* d_in, const int* in_sizes, int n_in,
                              void* d_out, int out_size) {
    (void)in_sizes; (void)n_in; (void)out_size;
    static float2* bufA = nullptr;
    static float2* bufB = nullptr;
    static float*  xh   = nullptr;
    static float*  z    = nullptr;
    if (!bufA) {
        cudaGetSymbolAddress((void**)&bufA, g_bufA);
        cudaGetSymbolAddress((void**)&bufB, g_bufB);
        cudaGetSymbolAddress((void**)&xh,   g_Xh);
        cudaGetSymbolAddress((void**)&z,    g_Z);
    }
    const float* x  = (const float*)d_in[0];   // [8,16,48,48,48]
    const float* wt = (const float*)d_in[2];   // [16,16,12,12,12]
    float* out = (float*)d_out;

    init_tw<<<(L * L + 255) / 256, 256>>>();

    ykernel1<<<(CF * 12 * 12 * L + 255) / 256, 256>>>(wt);
    ykernel2<<<(CF * 12 * L * L  + 255) / 256, 256>>>();
    ykernel3t<<<CF * L, 256>>>();

    // forward: x -> Xh (half-spectrum pipeline + dual-fold)
    pass_w<<<BF * L, 256>>>(x, bufA);
    pass_h<<<BF * L, 256>>>(bufA, bufB);
    pass_d<<<BF * L, 256>>>(bufB, xh, 1.f);

    mix2<<<(55296 / 4) + 1, 128>>>();

    // inverse: Z -> out, scaled by 1/N3
    pass_w<<<BF * L, 256>>>(z, bufA);
    pass_h<<<BF * L, 256>>>(bufA, bufB);
    pass_d<<<BF * L, 256>>>(bufB, out, 1.f / (float)N3);
}

// round 5
// speedup vs baseline: 2.3903x; 1.0434x over previous
#include <cuda_runtime.h>
#include <math.h>

#define L    48
#define LH   26                 // kept frequencies (Hermitian half: 0..25)
#define N3   110592             // 48^3
#define NHALF 55296             // N3/2
#define BF   128                // B*CIN  fields for x / Z
#define CF   256                // CIN*COUT fields for Y
#define PLH  59904              // 48*48*26

// ---------------- scratch (static device memory) ---------------------------
__device__ float2 g_tw[L * L];
__device__ float2 g_tw1[L];
__device__ float2 g_emp[L];
__device__ float2 g_bufB[BF * PLH];            // 61 MB (only one intermediate now)
__device__ float  g_Xh[BF * N3];
__device__ float  g_Yh[CF * N3];
__device__ float  g_Z [BF * N3];
__device__ float2 g_T1[CF * 12 * 12 * L];
__device__ float2 g_T2[CF * 12 * L * L];

// ---------------- twiddle init ---------------------------------------------
__global__ void init_tw() {
    int idx = blockIdx.x * blockDim.x + threadIdx.x;
    if (idx < L * L) {
        int k = idx / L, n = idx % L;
        int m = (k * n) % L;
        double a = -6.283185307179586476925286766559 * (double)m / (double)L;
        g_tw[idx] = make_float2((float)cos(a), (float)sin(a));
    }
    if (idx < L) {
        double a = -6.283185307179586476925286766559 * (double)idx / (double)L;
        float cx = (float)cos(a), cy = (float)sin(a);
        g_tw1[idx] = make_float2(cx, cy);
        g_emp[idx] = make_float2(cx - cy, cx + cy);
    }
}

// ============ fused pass W+H: real plane -> half spectrum [k_h][k_w] ========
// block = (field, d). Transforms w then h entirely in shared memory.
// out[(f*48+d)*48*26 + k_h*26 + k_w]  (complex)
__global__ __launch_bounds__(256) void pass_wh(
    const float* __restrict__ in, float2* __restrict__ out)
{
    __shared__ __align__(16) char ubuf[48 * 27 * sizeof(float2)];  // P / C overlay
    float  (*P)[49] = reinterpret_cast<float  (*)[49]>(ubuf);      // P[w][h]
    float2 (*C)[27] = reinterpret_cast<float2 (*)[27]>(ubuf);      // C[m_h][k_w]
    __shared__ float2 A2[L][L + 2];      // stage-1 (w) output A[m_w][h]
    __shared__ float2 B2[LH][L + 1];     // stage-2 (w) output Xw[k_w][h]
    __shared__ float2 TWs[L];

    int t = threadIdx.x;
    int f = blockIdx.x / L, d = blockIdx.x % L;
    const float* src = in + (size_t)f * N3 + (size_t)d * 2304;

    if (t < L) TWs[t] = g_tw1[t];
    for (int idx = t; idx < L * L; idx += 256)
        P[idx % L][idx / L] = src[idx];          // transpose: P[w][h]
    __syncthreads();

    int tx = t & 15, ty = t >> 4;
    int k1 = ty & 7;
    bool g1 = (tx < 10);
    int txg = g1 ? (tx + 16) : 0;                // clamped high column

    float2 w8[8];
    {
        int step = (6 * k1) % L, widx = 0;
        #pragma unroll
        for (int n1 = 0; n1 < 8; n1++) { w8[n1] = TWs[widx]; widx += step; if (widx >= L) widx -= L; }
    }

    // ---- stage 1 (w): A[m][h], m = ty+16a, h = tx+16b -----------------------
    {
        float ar[3][3] = {{0.f}}, ai[3][3] = {{0.f}};
        #pragma unroll
        for (int n1 = 0; n1 < 8; n1++) {
            float2 w = w8[n1];
            #pragma unroll
            for (int a = 0; a < 3; a++) {
                int row = 6 * n1 + ((ty + 16 * a) >> 3);
                #pragma unroll
                for (int b = 0; b < 3; b++) {
                    float p = P[row][tx + 16 * b];
                    ar[a][b] += p * w.x;  ai[a][b] += p * w.y;
                }
            }
        }
        #pragma unroll
        for (int a = 0; a < 3; a++)
            #pragma unroll
            for (int b = 0; b < 3; b++)
                A2[ty + 16 * a][tx + 16 * b] = make_float2(ar[a][b], ai[a][b]);
    }
    __syncthreads();

    // ---- stage 2 (w): Xw[k_w][h], k_w = tx+16c (<26), h = ty+16a ------------
    {
        float xr[3][2] = {{0.f}}, xi[3][2] = {{0.f}};
        int r8 = tx & 7;
        int i0 = 0, i1 = 0;
        int k3a = tx, k3b = tx + 16;
        #pragma unroll
        for (int n2 = 0; n2 < 6; n2++) {
            int arow = n2 * 8 + r8;
            float2 w0 = TWs[i0], w1 = TWs[i1];
            i0 += k3a; if (i0 >= L) i0 -= L;
            i1 += k3b; if (i1 >= L) i1 -= L;
            #pragma unroll
            for (int a = 0; a < 3; a++) {
                float2 v = A2[arow][ty + 16 * a];
                xr[a][0] += v.x * w0.x - v.y * w0.y;
                xi[a][0] += v.x * w0.y + v.y * w0.x;
                xr[a][1] += v.x * w1.x - v.y * w1.y;
                xi[a][1] += v.x * w1.y + v.y * w1.x;
            }
        }
        #pragma unroll
        for (int a = 0; a < 3; a++) {
            int h = ty + 16 * a;
            B2[k3a][h] = make_float2(xr[a][0], xi[a][0]);
            if (g1) B2[k3b][h] = make_float2(xr[a][1], xi[a][1]);
        }
    }
    __syncthreads();

    // ---- stage 3 (h, butterfly 1): C[m][k_w], m = ty+16a, k_w = tx+16b ------
    {
        float cr[3][2] = {{0.f}}, ci[3][2] = {{0.f}};
        #pragma unroll
        for (int n1 = 0; n1 < 8; n1++) {
            float2 w = w8[n1];
            #pragma unroll
            for (int a = 0; a < 3; a++) {
                int row = 6 * n1 + ((ty + 16 * a) >> 3);
                float2 q0 = B2[tx][row];
                float2 q1 = B2[txg][row];
                cr[a][0] += q0.x * w.x - q0.y * w.y;
                ci[a][0] += q0.x * w.y + q0.y * w.x;
                cr[a][1] += q1.x * w.x - q1.y * w.y;
                ci[a][1] += q1.x * w.y + q1.y * w.x;
            }
        }
        __syncthreads();                          // P region fully dead; reuse as C
        #pragma unroll
        for (int a = 0; a < 3; a++) {
            C[ty + 16 * a][tx] = make_float2(cr[a][0], ci[a][0]);
            if (g1) C[ty + 16 * a][tx + 16] = make_float2(cr[a][1], ci[a][1]);
        }
    }
    __syncthreads();

    // ---- stage 4 (h, butterfly 2): out[k_h][k_w] ----------------------------
    {
        float xr[3][2] = {{0.f}}, xi[3][2] = {{0.f}};
        int iw[3] = {0, 0, 0};
        #pragma unroll
        for (int n2 = 0; n2 < 6; n2++) {
            int arow = n2 * 8 + k1;
            float2 v0 = C[arow][tx];
            float2 v1 = C[arow][txg];
            #pragma unroll
            for (int a = 0; a < 3; a++) {
                float2 w = TWs[iw[a]];
                iw[a] += ty + 16 * a; if (iw[a] >= L) iw[a] -= L;
                xr[a][0] += v0.x * w.x - v0.y * w.y;
                xi[a][0] += v0.x * w.y + v0.y * w.x;
                xr[a][1] += v1.x * w.x - v1.y * w.y;
                xi[a][1] += v1.x * w.y + v1.y * w.x;
            }
        }
        float2* dst = out + (size_t)(f * L + d) * (L * LH);
        #pragma unroll
        for (int a = 0; a < 3; a++) {
            int k2 = ty + 16 * a;
            dst[(size_t)k2 * LH + tx] = make_float2(xr[a][0], xi[a][0]);
            if (g1) dst[(size_t)k2 * LH + tx + 16] = make_float2(xr[a][1], xi[a][1]);
        }
    }
}

// ============ pass D: complex, DFT along d, fold + Hermitian mirror write ===
__global__ __launch_bounds__(256) void pass_d(
    const float2* __restrict__ in, float* __restrict__ out, float scale)
{
    __shared__ float2 Q2[L][LH + 1];
    __shared__ float2 A2[L][LH + 1];
    __shared__ float2 TWs[L];
    int t = threadIdx.x;
    int f = blockIdx.x / L, k2 = blockIdx.x % L;
    const float2* src = in + ((size_t)f * (L * L) + k2) * LH;

    if (t < L) TWs[t] = g_tw1[t];
    for (int idx = t; idx < L * LH; idx += 256)
        Q2[idx / LH][idx % LH] = src[(size_t)(idx / LH) * (L * LH) + (idx % LH)];
    __syncthreads();

    int tx = t & 15, ty = t >> 4;
    bool g1 = (tx < 10);
    int txg = g1 ? (tx + 16) : 0;

    {
        int k1 = ty & 7;
        float2 w8[8];
        int step = (6 * k1) % L, widx = 0;
        #pragma unroll
        for (int n1 = 0; n1 < 8; n1++) { w8[n1] = TWs[widx]; widx += step; if (widx >= L) widx -= L; }

        float ar[3][2] = {{0.f}}, ai[3][2] = {{0.f}};
        #pragma unroll
        for (int n1 = 0; n1 < 8; n1++) {
            float2 w = w8[n1];
            #pragma unroll
            for (int a = 0; a < 3; a++) {
                int row = 6 * n1 + ((ty + 16 * a) >> 3);
                float2 q0 = Q2[row][tx];
                float2 q1 = Q2[row][txg];
                ar[a][0] += q0.x * w.x - q0.y * w.y;
                ai[a][0] += q0.x * w.y + q0.y * w.x;
                ar[a][1] += q1.x * w.x - q1.y * w.y;
                ai[a][1] += q1.x * w.y + q1.y * w.x;
            }
        }
        __syncthreads();
        #pragma unroll
        for (int a = 0; a < 3; a++) {
            A2[ty + 16 * a][tx] = make_float2(ar[a][0], ai[a][0]);
            if (g1) A2[ty + 16 * a][tx + 16] = make_float2(ar[a][1], ai[a][1]);
        }
    }
    __syncthreads();

    {
        int r8 = ty & 7;
        float xr[3][2] = {{0.f}}, xi[3][2] = {{0.f}};
        int iw[3] = {0, 0, 0};
        #pragma unroll
        for (int n2 = 0; n2 < 6; n2++) {
            int arow = n2 * 8 + r8;
            float2 v0 = A2[arow][tx];
            float2 v1 = A2[arow][txg];
            #pragma unroll
            for (int a = 0; a < 3; a++) {
                float2 w = TWs[iw[a]];
                iw[a] += ty + 16 * a; if (iw[a] >= L) iw[a] -= L;
                xr[a][0] += v0.x * w.x - v0.y * w.y;
                xi[a][0] += v0.x * w.y + v0.y * w.x;
                xr[a][1] += v1.x * w.x - v1.y * w.y;
                xi[a][1] += v1.x * w.y + v1.y * w.x;
            }
        }
        int mk2 = (k2 == 0) ? 0 : L - k2;
        float* dstD = out + (size_t)f * N3 + (size_t)k2 * L;
        float* dstM = out + (size_t)f * N3 + (size_t)mk2 * L;
        int k3a = tx, k3b = tx + 16;
        int m3a = (k3a == 0) ? 0 : L - k3a;
        int m3b = L - k3b;
        #pragma unroll
        for (int a = 0; a < 3; a++) {
            int k1 = ty + 16 * a;
            int mk1 = (k1 == 0) ? 0 : L - k1;
            dstD[(size_t)k1 * 2304 + k3a]  = scale * (xr[a][0] - xi[a][0]);
            dstM[(size_t)mk1 * 2304 + m3a] = scale * (xr[a][0] + xi[a][0]);
            if (g1) {
                dstD[(size_t)k1 * 2304 + k3b]  = scale * (xr[a][1] - xi[a][1]);
                dstM[(size_t)mk1 * 2304 + m3b] = scale * (xr[a][1] + xi[a][1]);
            }
        }
    }
}

// ---------------- Y path ----------------------------------------------------
__global__ void ykernel1(const float* __restrict__ w) {
    int idx = blockIdx.x * blockDim.x + threadIdx.x;
    if (idx >= CF * 12 * 12 * L) return;
    int k3 = idx % L;
    int r  = idx / L;
    const float* wp = w + r * 12;
    float ar = 0.f, ai = 0.f;
    #pragma unroll
    for (int n3 = 0; n3 < 12; n3++) {
        float2 e = g_tw[k3 * L + n3];
        float  v = wp[n3];
        ar += v * e.x;  ai += v * e.y;
    }
    g_T1[idx] = make_float2(ar, ai);
}

__global__ void ykernel2() {
    int idx = blockIdx.x * blockDim.x + threadIdx.x;
    if (idx >= CF * 12 * L * L) return;
    int k3 = idx % L;
    int k2 = (idx / L) % L;
    int r  = idx / (L * L);
    float ar = 0.f, ai = 0.f;
    #pragma unroll
    for (int n2 = 0; n2 < 12; n2++) {
        float2 tv = g_T1[(r * 12 + n2) * L + k3];
        float2 e  = g_tw[k2 * L + n2];
        ar += tv.x * e.x - tv.y * e.y;
        ai += tv.x * e.y + tv.y * e.x;
    }
    g_T2[idx] = make_float2(ar, ai);
}

__global__ __launch_bounds__(256) void ykernel3t() {
    __shared__ float2 Tc[12][L + 1];
    __shared__ float2 EMP[L];
    int t  = threadIdx.x;
    int io = blockIdx.x / L;
    int k2 = blockIdx.x % L;

    if (t < L) EMP[t] = g_emp[t];
    for (int idx = t; idx < 12 * L; idx += 256)
        Tc[idx / L][idx % L] = g_T2[(size_t)((io * 12 + idx / L) * L + k2) * L + (idx % L)];
    __syncthreads();

    int tx = t & 15, ty = t >> 4;
    float acc[3][3] = {{0.f}};
    int iw[3] = {0, 0, 0};
    #pragma unroll
    for (int n1 = 0; n1 < 12; n1++) {
        float2 tv[3];
        #pragma unroll
        for (int b = 0; b < 3; b++) tv[b] = Tc[n1][tx + 16 * b];
        #pragma unroll
        for (int a = 0; a < 3; a++) {
            float2 e = EMP[iw[a]];
            iw[a] += ty + 16 * a; if (iw[a] >= L) iw[a] -= L;
            #pragma unroll
            for (int b = 0; b < 3; b++)
                acc[a][b] += tv[b].x * e.x - tv[b].y * e.y;
        }
    }
    #pragma unroll
    for (int a = 0; a < 3; a++)
        #pragma unroll
        for (int b = 0; b < 3; b++)
            g_Yh[(size_t)io * N3 + (size_t)(ty + 16 * a) * 2304 + k2 * L + tx + 16 * b] = acc[a][b];
}

// ---------------- coalesced paired mix --------------------------------------
// block covers 16 consecutive k; mirrors are contiguous descending runs.
#define MK    16
#define MPIT  20
__global__ __launch_bounds__(256) void mix3() {
    extern __shared__ float sm[];
    float* Xa = sm;                       // [128][MPIT]
    float* Xb = Xa + 128 * MPIT;
    float* Ya = Xb + 128 * MPIT;          // [256][MPIT]
    float* Yb = Ya + 256 * MPIT;

    int t  = threadIdx.x;
    int k0 = blockIdx.x * MK;

    for (int q = t; q < 128 * MK; q += 256) {
        int kk = q & 15, bi = q >> 4;
        int k = k0 + kk; if (k > NHALF) k = NHALF;
        int sk = (k == 0) ? 0 : (N3 - k);
        Xa[bi * MPIT + kk] = g_Xh[(size_t)bi * N3 + k];
        Xb[bi * MPIT + kk] = g_Xh[(size_t)bi * N3 + sk];
    }
    for (int q = t; q < 256 * MK; q += 256) {
        int kk = q & 15, io = q >> 4;
        int k = k0 + kk; if (k > NHALF) k = NHALF;
        int sk = (k == 0) ? 0 : (N3 - k);
        Ya[io * MPIT + kk] = g_Yh[(size_t)io * N3 + k];
        Yb[io * MPIT + kk] = g_Yh[(size_t)io * N3 + sk];
    }
    __syncthreads();

    int kh = t >> 7;                      // 0/1: low/high 8 k
    int b  = (t >> 4) & 7;
    int o  = t & 15;

    float acc[8] = {0,0,0,0,0,0,0,0}, accs[8] = {0,0,0,0,0,0,0,0};
    #pragma unroll 4
    for (int i = 0; i < 16; i++) {
        const float* xa = Xa + (b * 16 + i) * MPIT + kh * 8;
        const float* xb = Xb + (b * 16 + i) * MPIT + kh * 8;
        const float* ya = Ya + (i * 16 + o) * MPIT + kh * 8;
        const float* yb = Yb + (i * 16 + o) * MPIT + kh * 8;
        float xk[8], xs[8], yk[8], ys[8];
        *(float4*)&xk[0] = *(const float4*)xa;      *(float4*)&xk[4] = *(const float4*)(xa + 4);
        *(float4*)&xs[0] = *(const float4*)xb;      *(float4*)&xs[4] = *(const float4*)(xb + 4);
        *(float4*)&yk[0] = *(const float4*)ya;      *(float4*)&yk[4] = *(const float4*)(ya + 4);
        *(float4*)&ys[0] = *(const float4*)yb;      *(float4*)&ys[4] = *(const float4*)(yb + 4);
        #pragma unroll
        for (int kk = 0; kk < 8; kk++) {
            float xe = 0.5f * (xk[kk] + xs[kk]);
            float xo = 0.5f * (xk[kk] - xs[kk]);
            acc[kk]  += xe * yk[kk] + xo * ys[kk];
            accs[kk] += xe * ys[kk] - xo * yk[kk];
        }
    }

    int kb = k0 + kh * 8;
    float* zrow = g_Z + (size_t)(b * 16 + o) * N3;
    if (kb + 7 <= NHALF) {
        *(float4*)(zrow + kb)     = make_float4(acc[0], acc[1], acc[2], acc[3]);
        *(float4*)(zrow + kb + 4) = make_float4(acc[4], acc[5], acc[6], acc[7]);
    } else {
        #pragma unroll
        for (int kk = 0; kk < 8; kk++)
            if (kb + kk <= NHALF) zrow[kb + kk] = acc[kk];
    }
    #pragma unroll
    for (int kk = 0; kk < 8; kk++) {
        int k = kb + kk;
        if (k >= 1 && k <= NHALF - 1) zrow[N3 - k] = accs[kk];
    }
}

// ---------------- launcher ---------------------------------------------------
extern "C" void kernel_launch(void* const* d_in, const int* in_sizes, int n_in,
                              void* d_out, int out_size) {
    (void)in_sizes; (void)n_in; (void)out_size;
    static float2* bufB = nullptr;
    static float*  xh   = nullptr;
    static float*  z    = nullptr;
    if (!bufB) {
        cudaGetSymbolAddress((void**)&bufB, g_bufB);
        cudaGetSymbolAddress((void**)&xh,   g_Xh);
        cudaGetSymbolAddress((void**)&z,    g_Z);
        cudaFuncSetAttribute(mix3, cudaFuncAttributeMaxDynamicSharedMemorySize,
                             (128 * MPIT * 2 + 256 * MPIT * 2) * (int)sizeof(float));
    }
    const float* x  = (const float*)d_in[0];   // [8,16,48,48,48]
    const float* wt = (const float*)d_in[2];   // [16,16,12,12,12]
    float* out = (float*)d_out;

    const int mix_smem = (128 * MPIT * 2 + 256 * MPIT * 2) * (int)sizeof(float);
    const int mix_grid = NHALF / MK + 1;       // 3457, last block: kk=0 only

    init_tw<<<(L * L + 255) / 256, 256>>>();

    ykernel1<<<(CF * 12 * 12 * L + 255) / 256, 256>>>(wt);
    ykernel2<<<(CF * 12 * L * L  + 255) / 256, 256>>>();
    ykernel3t<<<CF * L, 256>>>();

    // forward: x -> Xh
    pass_wh<<<BF * L, 256>>>(x, bufB);
    pass_d <<<BF * L, 256>>>(bufB, xh, 1.f);

    mix3<<<mix_grid, 256, mix_smem>>>();

    // inverse: Z -> out (scaled 1/N3)
    pass_wh<<<BF * L, 256>>>(z, bufB);
    pass_d <<<BF * L, 256>>>(bufB, out, 1.f / (float)N3);
}